// round 6
// baseline (speedup 1.0000x reference)
#include <cuda_runtime.h>
#include <math.h>

#define BB 2
#define SS 2048
#define DD 1024
#define HH 16
#define HDD 64
#define MR (BB*SS)   // 4096 rows

// Scratch (allocation-free rule: __device__ globals)
__device__ __align__(16) float    g_kv[MR * 2 * DD];   // kv out (rounded, K-halves permuted)
__device__ __align__(16) float    g_q [MR * DD];       // q out (rounded, logical layout)
__device__ __align__(16) float    g_av[MR * DD];       // attn out (rounded, A-permuted)
__device__ __align__(16) unsigned g_xc  [MR * DD];     // x     tf32 bits, A-perm
__device__ __align__(16) unsigned g_yc  [MR * DD];     // y     tf32 bits, A-perm
__device__ __align__(16) unsigned g_wkvc[DD * 2 * DD]; // W_kv  tf32 bits, B-perm
__device__ __align__(16) unsigned g_wqc [DD * DD];     // W_q   tf32 bits, B-perm
__device__ __align__(16) unsigned g_woc [DD * DD];     // W_o   tf32 bits, B-perm

#define FULLMASK 0xffffffffu

__device__ __forceinline__ unsigned f2tf32(float f) {
    unsigned u;
    asm("cvt.rna.tf32.f32 %0, %1;" : "=r"(u) : "f"(f));
    return u;
}

__device__ __forceinline__ void mma_tf32(float* d, const unsigned* a,
                                         unsigned b0, unsigned b1) {
    asm volatile(
        "mma.sync.aligned.m16n8k8.row.col.f32.tf32.tf32.f32 "
        "{%0,%1,%2,%3}, {%4,%5,%6,%7}, {%8,%9}, {%0,%1,%2,%3};\n"
        : "+f"(d[0]), "+f"(d[1]), "+f"(d[2]), "+f"(d[3])
        : "r"(a[0]), "r"(a[1]), "r"(a[2]), "r"(a[3]), "r"(b0), "r"(b1));
}

__device__ __forceinline__ void cp16(void* dst_smem, const void* src) {
    unsigned d = (unsigned)__cvta_generic_to_shared(dst_smem);
    asm volatile("cp.async.cg.shared.global [%0], [%1], 16;\n" :: "r"(d), "l"(src));
}
__device__ __forceinline__ void cp_commit() {
    asm volatile("cp.async.commit_group;\n");
}
template <int N> __device__ __forceinline__ void cp_wait() {
    asm volatile("cp.async.wait_group %0;\n" :: "n"(N));
}

// Output permutation for kv-GEMM: K-halves (c<64 within 128-col head group)
// get per-32 A-style perm so attention K fragment reads are LDS.128.
__device__ __forceinline__ int perm_kv(int n) {
    int hc = n & 127;
    if (hc < 64) {
        int c = hc & 31;
        return (n & ~127) | (hc & 32) | ((c & 3) << 3) | (c >> 2);
    }
    return n;
}

// ---------------------------------------------------------------------------
// Pre-round + permute passes
// A-perm (within 32-col groups):  p(c) = (c&3)*8 + (c>>2)
// B-perm (within 128-col groups): p(n) = (n&7)*16 + (n>>3)
// ---------------------------------------------------------------------------
__global__ __launch_bounds__(256) void cvtA_kernel(
    const float* __restrict__ src, unsigned* __restrict__ dst, int n4)
{
    int i = blockIdx.x * 256 + threadIdx.x;
    if (i >= n4) return;
    size_t base = 4 * (size_t)i;
    float4 v = *(const float4*)(src + base);
    int c = (int)(base & 31);            // c&3 == 0
    size_t wp = (base & ~(size_t)31) + (c >> 2);
    dst[wp     ] = f2tf32(v.x);
    dst[wp +  8] = f2tf32(v.y);
    dst[wp + 16] = f2tf32(v.z);
    dst[wp + 24] = f2tf32(v.w);
}

__global__ __launch_bounds__(256) void cvtB_kernel(
    const float* __restrict__ src, unsigned* __restrict__ dst, int n4)
{
    int i = blockIdx.x * 256 + threadIdx.x;
    if (i >= n4) return;
    size_t base = 4 * (size_t)i;
    float4 v = *(const float4*)(src + base);
    int c = (int)(base & 127);           // c&3 == 0
    size_t wp = (base & ~(size_t)127) + ((size_t)(c & 7) * 16) + (c >> 3);
    dst[wp     ] = f2tf32(v.x);
    dst[wp + 16] = f2tf32(v.y);
    dst[wp + 32] = f2tf32(v.z);
    dst[wp + 48] = f2tf32(v.w);
}

// ---------------------------------------------------------------------------
// Tensor-core tf32 GEMM, cp.async 2-stage, LDS.128 fragment loads.
// A gmem pre-permuted per-32 (k-dim), B gmem pre-permuted per-128 (n-dim).
// As[m][*] stride 36: thread t's 8 A-words at m*36+8t  (banks 4g+8t, CF)
// Bs[k][*] stride 132: thread's 8 B-words at k*132+16g+wn/8 (banks 4t+16g, CF)
// PERM: 0 = plain output, 1 = kv output perm. ROUND: tf32 pre-round output.
// ---------------------------------------------------------------------------
#define TBM 128
#define TBN 128
#define TBK 32
#define ASTR 36
#define BSTR 132
#define ABUF (TBM * ASTR)   // 4608 words
#define BBUF (TBK * BSTR)   // 4224 words
#define GEMM_SMEM ((2 * ABUF + 2 * BBUF) * 4)  // 70656 bytes

template <int ROUND, int PERM>
__global__ __launch_bounds__(256, 2) void gemm_tc_kernel(
    const unsigned* __restrict__ A, const unsigned* __restrict__ Bm,
    const float* __restrict__ bias, float* __restrict__ C,
    int M, int N, int K)
{
    extern __shared__ unsigned smg[];
    unsigned* As = smg;                 // [2][ABUF]
    unsigned* Bs = smg + 2 * ABUF;      // [2][BBUF]

    const int tid  = threadIdx.x;
    const int w    = tid >> 5;
    const int lane = tid & 31;
    const int g    = lane >> 2;
    const int t    = lane & 3;
    const int wm   = (w & 3) * 32;
    const int wn   = (w >> 2) * 64;
    const int brow = blockIdx.y * TBM;
    const int bcol = blockIdx.x * TBN;

    float acc[2][8][4];
    #pragma unroll
    for (int mt = 0; mt < 2; mt++)
        #pragma unroll
        for (int nt = 0; nt < 8; nt++)
            #pragma unroll
            for (int j = 0; j < 4; j++) acc[mt][nt][j] = 0.f;

    auto load_tile = [&](int k0, int buf) {
        #pragma unroll
        for (int it = 0; it < 4; it++) {
            int i  = it * 256 + tid;
            int m  = i >> 3;
            int c4 = (i & 7) * 4;
            cp16(&As[buf * ABUF + m * ASTR + c4],
                 A + (size_t)(brow + m) * K + k0 + c4);
        }
        #pragma unroll
        for (int it = 0; it < 4; it++) {
            int i  = it * 256 + tid;
            int kk = i >> 5;
            int c4 = (i & 31) * 4;
            cp16(&Bs[buf * BBUF + kk * BSTR + c4],
                 Bm + (size_t)(k0 + kk) * N + bcol + c4);
        }
        cp_commit();
    };

    load_tile(0, 0);
    int buf = 0;
    for (int k0 = 0; k0 < K; k0 += TBK, buf ^= 1) {
        if (k0 + TBK < K) { load_tile(k0 + TBK, buf ^ 1); cp_wait<1>(); }
        else              { cp_wait<0>(); }
        __syncthreads();

        const unsigned* Ab = &As[buf * ABUF];
        const unsigned* Bb = &Bs[buf * BBUF];

        // A fragments for the whole tile: 4 rows x 8 words (8 LDS.128)
        unsigned ar[4][8];
        #pragma unroll
        for (int mt = 0; mt < 2; mt++)
            #pragma unroll
            for (int hh = 0; hh < 2; hh++) {
                const unsigned* p = &Ab[(wm + mt * 16 + g + 8 * hh) * ASTR + 8 * t];
                *(uint4*)&ar[mt * 2 + hh][0] = *(const uint4*)p;
                *(uint4*)&ar[mt * 2 + hh][4] = *(const uint4*)(p + 4);
            }

        #pragma unroll
        for (int ks = 0; ks < TBK / 8; ks++) {
            unsigned br0[8], br1[8];
            const unsigned* p0 = &Bb[(8 * ks + t) * BSTR + 16 * g + wn / 8];
            const unsigned* p1 = &Bb[(8 * ks + t + 4) * BSTR + 16 * g + wn / 8];
            *(uint4*)&br0[0] = *(const uint4*)p0;
            *(uint4*)&br0[4] = *(const uint4*)(p0 + 4);
            *(uint4*)&br1[0] = *(const uint4*)p1;
            *(uint4*)&br1[4] = *(const uint4*)(p1 + 4);

            unsigned af0[4] = {ar[0][2 * ks], ar[1][2 * ks],
                               ar[0][2 * ks + 1], ar[1][2 * ks + 1]};
            unsigned af1[4] = {ar[2][2 * ks], ar[3][2 * ks],
                               ar[2][2 * ks + 1], ar[3][2 * ks + 1]};
            #pragma unroll
            for (int nt = 0; nt < 8; nt++) {
                mma_tf32(acc[0][nt], af0, br0[nt], br1[nt]);
                mma_tf32(acc[1][nt], af1, br0[nt], br1[nt]);
            }
        }
        __syncthreads();
    }

    // Epilogue
    #pragma unroll
    for (int mt = 0; mt < 2; mt++) {
        const size_t r0 = (size_t)(brow + wm + mt * 16 + g);
        float* c0 = C + r0 * N;
        float* c1 = c0 + (size_t)8 * N;
        #pragma unroll
        for (int nt = 0; nt < 8; nt++) {
            int nc = bcol + wn + nt * 8 + 2 * t;
            float bx = bias[nc], by = bias[nc + 1];
            float v00 = acc[mt][nt][0] + bx, v01 = acc[mt][nt][1] + by;
            float v10 = acc[mt][nt][2] + bx, v11 = acc[mt][nt][3] + by;
            if (ROUND) {
                v00 = __uint_as_float(f2tf32(v00));
                v01 = __uint_as_float(f2tf32(v01));
                v10 = __uint_as_float(f2tf32(v10));
                v11 = __uint_as_float(f2tf32(v11));
            }
            if (PERM == 1) {
                int pc0 = perm_kv(nc), pc1 = perm_kv(nc + 1);
                c0[pc0] = v00; c0[pc1] = v01;
                c1[pc0] = v10; c1[pc1] = v11;
            } else {
                *(float2*)&c0[nc] = make_float2(v00, v01);
                *(float2*)&c1[nc] = make_float2(v10, v11);
            }
        }
    }
}

// ---------------------------------------------------------------------------
// Tensor-core flash attention, cp.async 2-stage.
// K-halves of g_kv are pre-permuted (per-32 of d) -> K fragment reads are
// LDS.128 (4 per key row, banks 4g+8t, conflict-free). V unpermuted,
// stride 72 scalar reads (banks 8t+g, conflict-free).
// Output written (B,H,S,HD)-contiguous, tf32-pre-rounded, A-permuted
// (per-32 of the d column) for the o-projection.
// ---------------------------------------------------------------------------
#define KSTRIDE 68
#define VSTRIDE 72
#define KBUF (64 * KSTRIDE)   // 4352 words
#define VBUF (64 * VSTRIDE)   // 4608 words
#define ATTN_SMEM ((2 * KBUF + 2 * VBUF) * 4)  // 71680 bytes

__global__ __launch_bounds__(256) void attn_tc_kernel(
    const float* __restrict__ q, const float* __restrict__ kv,
    float* __restrict__ out)
{
    extern __shared__ unsigned sma[];
    unsigned* k_u = sma;              // [2][KBUF]
    unsigned* v_u = sma + 2 * KBUF;   // [2][VBUF]

    const int tid  = threadIdx.x;
    const int w    = tid >> 5;
    const int lane = tid & 31;
    const int g    = lane >> 2;
    const int t    = lane & 3;
    const int bh   = blockIdx.y;
    const int b    = bh / HH;
    const int h    = bh % HH;
    const int q0   = blockIdx.x * 128;

    const float* kvbase = kv + (size_t)b * SS * (2 * DD) + h * (2 * HDD);

    auto load_kv = [&](int kt, int buf) {
        #pragma unroll
        for (int it = 0; it < 4; it++) {
            int idx = it * 256 + tid;
            int row = idx >> 4;
            int c4  = (idx & 15) * 4;
            const float* src = kvbase + (size_t)(kt + row) * (2 * DD) + c4;
            cp16(&k_u[buf * KBUF + row * KSTRIDE + c4], src);
            cp16(&v_u[buf * VBUF + row * VSTRIDE + c4], src + HDD);
        }
        cp_commit();
    };

    load_kv(0, 0);

    // Q fragments (logical layout; x0.125 exponent-only => tf32-exact)
    unsigned qa[8][4];
    {
        const float* q0p = q + (size_t)(b * SS + q0 + w * 16 + g) * DD + h * HDD;
        const float* q1p = q0p + (size_t)8 * DD;
        #pragma unroll
        for (int kj = 0; kj < 8; kj++) {
            qa[kj][0] = __float_as_uint(q0p[8 * kj + t]     * 0.125f);
            qa[kj][1] = __float_as_uint(q1p[8 * kj + t]     * 0.125f);
            qa[kj][2] = __float_as_uint(q0p[8 * kj + t + 4] * 0.125f);
            qa[kj][3] = __float_as_uint(q1p[8 * kj + t + 4] * 0.125f);
        }
    }

    float o[8][4];
    #pragma unroll
    for (int i = 0; i < 8; i++)
        #pragma unroll
        for (int j = 0; j < 4; j++) o[i][j] = 0.f;
    float m0 = -INFINITY, m1 = -INFINITY, l0 = 0.f, l1 = 0.f;

    int buf = 0;
    for (int kt = 0; kt < SS; kt += 64, buf ^= 1) {
        if (kt + 64 < SS) { load_kv(kt + 64, buf ^ 1); cp_wait<1>(); }
        else              { cp_wait<0>(); }
        __syncthreads();

        const unsigned* kb = &k_u[buf * KBUF];
        const unsigned* vb = &v_u[buf * VBUF];

        // S = (Q * scale) @ K^T — K frags via LDS.128 (permuted layout)
        float s[8][4];
        #pragma unroll
        for (int nt = 0; nt < 8; nt++) {
            s[nt][0] = s[nt][1] = s[nt][2] = s[nt][3] = 0.f;
            const unsigned* kr = &kb[(8 * nt + g) * KSTRIDE + 8 * t];
            unsigned kr16[16];
            *(uint4*)&kr16[0]  = *(const uint4*)kr;
            *(uint4*)&kr16[4]  = *(const uint4*)(kr + 4);
            *(uint4*)&kr16[8]  = *(const uint4*)(kr + 32);
            *(uint4*)&kr16[12] = *(const uint4*)(kr + 36);
            #pragma unroll
            for (int kj = 0; kj < 8; kj++)
                mma_tf32(s[nt], qa[kj], kr16[2 * kj], kr16[2 * kj + 1]);
        }

        // Online softmax (rows r0 = 16w+g, r1 = r0+8)
        float rmax0 = -INFINITY, rmax1 = -INFINITY;
        #pragma unroll
        for (int nt = 0; nt < 8; nt++) {
            rmax0 = fmaxf(rmax0, fmaxf(s[nt][0], s[nt][1]));
            rmax1 = fmaxf(rmax1, fmaxf(s[nt][2], s[nt][3]));
        }
        rmax0 = fmaxf(rmax0, __shfl_xor_sync(FULLMASK, rmax0, 1));
        rmax0 = fmaxf(rmax0, __shfl_xor_sync(FULLMASK, rmax0, 2));
        rmax1 = fmaxf(rmax1, __shfl_xor_sync(FULLMASK, rmax1, 1));
        rmax1 = fmaxf(rmax1, __shfl_xor_sync(FULLMASK, rmax1, 2));

        const float mn0 = fmaxf(m0, rmax0);
        const float mn1 = fmaxf(m1, rmax1);
        const float cr0 = __expf(m0 - mn0);
        const float cr1 = __expf(m1 - mn1);
        m0 = mn0; m1 = mn1;
        l0 *= cr0; l1 *= cr1;
        #pragma unroll
        for (int nt = 0; nt < 8; nt++) {
            o[nt][0] *= cr0; o[nt][1] *= cr0;
            o[nt][2] *= cr1; o[nt][3] *= cr1;
        }

        // exp, row-sum, P -> A-fragment layout via shuffles
        const int srcA = (lane & 28) | (t >> 1);
        const int srcB = srcA | 2;
        const bool odd = (t & 1);
        unsigned pa[8][4];
        float ls0 = 0.f, ls1 = 0.f;
        #pragma unroll
        for (int nt = 0; nt < 8; nt++) {
            float p0 = __expf(s[nt][0] - mn0);
            float p1 = __expf(s[nt][1] - mn0);
            float p2 = __expf(s[nt][2] - mn1);
            float p3 = __expf(s[nt][3] - mn1);
            ls0 += p0 + p1; ls1 += p2 + p3;
            unsigned e0 = f2tf32(p0), e1 = f2tf32(p1);
            unsigned e2 = f2tf32(p2), e3 = f2tf32(p3);
            unsigned u0 = __shfl_sync(FULLMASK, e0, srcA);
            unsigned u1 = __shfl_sync(FULLMASK, e1, srcA);
            unsigned u2 = __shfl_sync(FULLMASK, e2, srcA);
            unsigned u3 = __shfl_sync(FULLMASK, e3, srcA);
            unsigned w0 = __shfl_sync(FULLMASK, e0, srcB);
            unsigned w1 = __shfl_sync(FULLMASK, e1, srcB);
            unsigned w2 = __shfl_sync(FULLMASK, e2, srcB);
            unsigned w3 = __shfl_sync(FULLMASK, e3, srcB);
            pa[nt][0] = odd ? u1 : u0;
            pa[nt][1] = odd ? u3 : u2;
            pa[nt][2] = odd ? w1 : w0;
            pa[nt][3] = odd ? w3 : w2;
        }
        ls0 += __shfl_xor_sync(FULLMASK, ls0, 1);
        ls0 += __shfl_xor_sync(FULLMASK, ls0, 2);
        ls1 += __shfl_xor_sync(FULLMASK, ls1, 1);
        ls1 += __shfl_xor_sync(FULLMASK, ls1, 2);
        l0 += ls0; l1 += ls1;

        // O += P @ V
        #pragma unroll
        for (int nd = 0; nd < 8; nd++) {
            #pragma unroll
            for (int kj = 0; kj < 8; kj++) {
                unsigned b0 = vb[(8 * kj + t)     * VSTRIDE + 8 * nd + g];
                unsigned b1 = vb[(8 * kj + t + 4) * VSTRIDE + 8 * nd + g];
                mma_tf32(o[nd], pa[kj], b0, b1);
            }
        }
        __syncthreads();
    }

    // normalize + pre-round + store (B,H,S,HD), A-permuted columns
    const float inv0 = 1.f / l0;
    const float inv1 = 1.f / l1;
    const size_t r0 = (size_t)(b * HH + h) * SS + q0 + w * 16 + g;
    float* o0 = out + r0 * HDD;
    float* o1 = o0 + (size_t)8 * HDD;
    #pragma unroll
    for (int nt = 0; nt < 8; nt++) {
        int c0 = 8 * nt + 2 * t;
        int c1 = c0 + 1;
        int p0 = (c0 & 32) | ((c0 & 3) << 3) | ((c0 & 31) >> 2);
        int p1 = (c1 & 32) | ((c1 & 3) << 3) | ((c1 & 31) >> 2);
        o0[p0] = __uint_as_float(f2tf32(o[nt][0] * inv0));
        o0[p1] = __uint_as_float(f2tf32(o[nt][1] * inv0));
        o1[p0] = __uint_as_float(f2tf32(o[nt][2] * inv1));
        o1[p1] = __uint_as_float(f2tf32(o[nt][3] * inv1));
    }
}

// ---------------------------------------------------------------------------
extern "C" void kernel_launch(void* const* d_in, const int* in_sizes, int n_in,
                              void* d_out, int out_size)
{
    const float* x    = (const float*)d_in[0];
    const float* y    = (const float*)d_in[1];
    const float* W_kv = (const float*)d_in[2];
    const float* b_kv = (const float*)d_in[3];
    const float* W_q  = (const float*)d_in[4];
    const float* b_q  = (const float*)d_in[5];
    const float* W_o  = (const float*)d_in[6];
    const float* b_o  = (const float*)d_in[7];
    float* out = (float*)d_out;

    float *kvp, *qp, *avp;
    unsigned *xc, *yc, *wkvc, *wqc, *woc;
    cudaGetSymbolAddress((void**)&kvp,  g_kv);
    cudaGetSymbolAddress((void**)&qp,   g_q);
    cudaGetSymbolAddress((void**)&avp,  g_av);
    cudaGetSymbolAddress((void**)&xc,   g_xc);
    cudaGetSymbolAddress((void**)&yc,   g_yc);
    cudaGetSymbolAddress((void**)&wkvc, g_wkvc);
    cudaGetSymbolAddress((void**)&wqc,  g_wqc);
    cudaGetSymbolAddress((void**)&woc,  g_woc);

    cudaFuncSetAttribute(gemm_tc_kernel<1, 1>,
        cudaFuncAttributeMaxDynamicSharedMemorySize, GEMM_SMEM);
    cudaFuncSetAttribute(gemm_tc_kernel<1, 0>,
        cudaFuncAttributeMaxDynamicSharedMemorySize, GEMM_SMEM);
    cudaFuncSetAttribute(gemm_tc_kernel<0, 0>,
        cudaFuncAttributeMaxDynamicSharedMemorySize, GEMM_SMEM);
    cudaFuncSetAttribute(attn_tc_kernel,
        cudaFuncAttributeMaxDynamicSharedMemorySize, ATTN_SMEM);

    dim3 blk(256);

    // Pre-round + permute operands
    cvtA_kernel<<<(MR * DD / 4 + 255) / 256, blk>>>(x, xc, MR * DD / 4);
    cvtA_kernel<<<(MR * DD / 4 + 255) / 256, blk>>>(y, yc, MR * DD / 4);
    cvtB_kernel<<<(DD * 2 * DD / 4 + 255) / 256, blk>>>(W_kv, wkvc, DD * 2 * DD / 4);
    cvtB_kernel<<<(DD * DD / 4 + 255) / 256, blk>>>(W_q, wqc, DD * DD / 4);
    cvtB_kernel<<<(DD * DD / 4 + 255) / 256, blk>>>(W_o, woc, DD * DD / 4);

    // kv = x @ W_kv + b_kv, output rounded + K-halves permuted
    gemm_tc_kernel<1, 1><<<dim3((2 * DD) / TBN, MR / TBM), blk, GEMM_SMEM>>>(
        xc, wkvc, b_kv, kvp, MR, 2 * DD, DD);
    // q = y @ W_q + b_q, output rounded, logical layout
    gemm_tc_kernel<1, 0><<<dim3(DD / TBN, MR / TBM), blk, GEMM_SMEM>>>(
        yc, wqc, b_q, qp, MR, DD, DD);

    // fused attention -> g_av (rounded, A-permuted, (B,H,S,HD) layout)
    attn_tc_kernel<<<dim3(SS / 128, BB * HH), blk, ATTN_SMEM>>>(qp, kvp, avp);

    // out = values @ W_o + b_o (plain output)
    gemm_tc_kernel<0, 0><<<dim3(DD / TBN, MR / TBM), blk, GEMM_SMEM>>>(
        (const unsigned*)avp, woc, b_o, out, MR, DD, DD);
}

// round 7
// speedup vs baseline: 1.0436x; 1.0436x over previous
#include <cuda_runtime.h>
#include <math.h>

#define BB 2
#define SS 2048
#define DD 1024
#define HH 16
#define HDD 64
#define MR (BB*SS)   // 4096 rows

// Scratch (allocation-free rule: __device__ globals)
__device__ __align__(16) float    g_kv[MR * 2 * DD];   // kv proj out (tf32-rounded)
__device__ __align__(16) float    g_q [MR * DD];       // q  proj out (tf32-rounded)
__device__ __align__(16) float    g_av[MR * DD];       // attn out (B,H,S,HD), rounded
__device__ __align__(16) unsigned g_xc  [MR * DD];     // x     tf32 bits (plain)
__device__ __align__(16) unsigned g_yc  [MR * DD];     // y     tf32 bits (plain)
__device__ __align__(16) unsigned g_wkvc[DD * 2 * DD]; // W_kv  tf32 bits, B-perm
__device__ __align__(16) unsigned g_wqc [DD * DD];     // W_q   tf32 bits, B-perm
__device__ __align__(16) unsigned g_woc [DD * DD];     // W_o   tf32 bits, B-perm

#define FULLMASK 0xffffffffu

__device__ __forceinline__ unsigned f2tf32(float f) {
    unsigned u;
    asm("cvt.rna.tf32.f32 %0, %1;" : "=r"(u) : "f"(f));
    return u;
}

__device__ __forceinline__ void mma_tf32(float* d, const unsigned* a,
                                         unsigned b0, unsigned b1) {
    asm volatile(
        "mma.sync.aligned.m16n8k8.row.col.f32.tf32.tf32.f32 "
        "{%0,%1,%2,%3}, {%4,%5,%6,%7}, {%8,%9}, {%0,%1,%2,%3};\n"
        : "+f"(d[0]), "+f"(d[1]), "+f"(d[2]), "+f"(d[3])
        : "r"(a[0]), "r"(a[1]), "r"(a[2]), "r"(a[3]), "r"(b0), "r"(b1));
}

__device__ __forceinline__ void cp16(void* dst_smem, const void* src) {
    unsigned d = (unsigned)__cvta_generic_to_shared(dst_smem);
    asm volatile("cp.async.cg.shared.global [%0], [%1], 16;\n" :: "r"(d), "l"(src));
}
__device__ __forceinline__ void cp_commit() {
    asm volatile("cp.async.commit_group;\n");
}
template <int N> __device__ __forceinline__ void cp_wait() {
    asm volatile("cp.async.wait_group %0;\n" :: "n"(N));
}

// ---------------------------------------------------------------------------
// Pre-round passes (grid-stride x4 for MLP)
// cvtA: plain tf32 round (A operands keep logical layout)
// cvtB: tf32 round + per-128-col perm  p(n) = (n&7)*16 + (n>>3)
// ---------------------------------------------------------------------------
__global__ __launch_bounds__(256) void cvtA_kernel(
    const float* __restrict__ src, unsigned* __restrict__ dst, int n4)
{
    int stride = gridDim.x * 256;
    for (int i = blockIdx.x * 256 + threadIdx.x; i < n4; i += stride) {
        float4 v = *(const float4*)(src + 4 * (size_t)i);
        uint4 u = make_uint4(f2tf32(v.x), f2tf32(v.y), f2tf32(v.z), f2tf32(v.w));
        *(uint4*)(dst + 4 * (size_t)i) = u;
    }
}

__global__ __launch_bounds__(256) void cvtB_kernel(
    const float* __restrict__ src, unsigned* __restrict__ dst, int n4)
{
    int stride = gridDim.x * 256;
    for (int i = blockIdx.x * 256 + threadIdx.x; i < n4; i += stride) {
        size_t base = 4 * (size_t)i;
        float4 v = *(const float4*)(src + base);
        int c = (int)(base & 127);           // c&3 == 0
        size_t wp = (base & ~(size_t)127) + ((size_t)(c & 7) * 16) + (c >> 3);
        dst[wp     ] = f2tf32(v.x);
        dst[wp + 16] = f2tf32(v.y);
        dst[wp + 32] = f2tf32(v.z);
        dst[wp + 48] = f2tf32(v.w);
    }
}

// ---------------------------------------------------------------------------
// Tensor-core tf32 GEMM, cp.async 2-stage.
// A: logical layout, scalar fragment loads (As stride 36, banks 4g+t, CF).
// B: gmem pre-permuted per-128 -> thread's 8 nt-words contiguous in smem
//    (Bs stride 132, 4 x LDS.128 per ks, conflict-free).
// ROUND: epilogue pre-rounds output to tf32 for the next consumer.
// ---------------------------------------------------------------------------
#define TBM 128
#define TBN 128
#define TBK 32
#define ASTR 36
#define BSTR 132
#define ABUF (TBM * ASTR)   // 4608 words
#define BBUF (TBK * BSTR)   // 4224 words
#define GEMM_SMEM ((2 * ABUF + 2 * BBUF) * 4)  // 70656 bytes

template <int ROUND>
__global__ __launch_bounds__(256, 2) void gemm_tc_kernel(
    const unsigned* __restrict__ A, const unsigned* __restrict__ Bm,
    const float* __restrict__ bias, float* __restrict__ C,
    int M, int N, int K)
{
    extern __shared__ unsigned smg[];
    unsigned* As = smg;                 // [2][ABUF]
    unsigned* Bs = smg + 2 * ABUF;      // [2][BBUF]

    const int tid  = threadIdx.x;
    const int w    = tid >> 5;
    const int lane = tid & 31;
    const int g    = lane >> 2;
    const int t    = lane & 3;
    const int wm   = (w & 3) * 32;
    const int wn   = (w >> 2) * 64;
    const int brow = blockIdx.y * TBM;
    const int bcol = blockIdx.x * TBN;

    float acc[2][8][4];
    #pragma unroll
    for (int mt = 0; mt < 2; mt++)
        #pragma unroll
        for (int nt = 0; nt < 8; nt++)
            #pragma unroll
            for (int j = 0; j < 4; j++) acc[mt][nt][j] = 0.f;

    auto load_tile = [&](int k0, int buf) {
        #pragma unroll
        for (int it = 0; it < 4; it++) {
            int i  = it * 256 + tid;
            int m  = i >> 3;
            int c4 = (i & 7) * 4;
            cp16(&As[buf * ABUF + m * ASTR + c4],
                 A + (size_t)(brow + m) * K + k0 + c4);
        }
        #pragma unroll
        for (int it = 0; it < 4; it++) {
            int i  = it * 256 + tid;
            int kk = i >> 5;
            int c4 = (i & 31) * 4;
            cp16(&Bs[buf * BBUF + kk * BSTR + c4],
                 Bm + (size_t)(k0 + kk) * N + bcol + c4);
        }
        cp_commit();
    };

    load_tile(0, 0);
    int buf = 0;
    for (int k0 = 0; k0 < K; k0 += TBK, buf ^= 1) {
        if (k0 + TBK < K) { load_tile(k0 + TBK, buf ^ 1); cp_wait<1>(); }
        else              { cp_wait<0>(); }
        __syncthreads();

        const unsigned* Ab = &As[buf * ABUF];
        const unsigned* Bb = &Bs[buf * BBUF];
        #pragma unroll
        for (int ks = 0; ks < TBK / 8; ks++) {
            // A fragments: scalar (unchanged from R5, no register bloat)
            unsigned af[2][4];
            #pragma unroll
            for (int mt = 0; mt < 2; mt++) {
                const unsigned* ab = &Ab[(wm + mt * 16) * ASTR + ks * 8];
                af[mt][0] = ab[g * ASTR + t];
                af[mt][1] = ab[(g + 8) * ASTR + t];
                af[mt][2] = ab[g * ASTR + t + 4];
                af[mt][3] = ab[(g + 8) * ASTR + t + 4];
            }
            // B fragments: 4 x LDS.128 (permuted layout)
            unsigned br0[8], br1[8];
            const unsigned* p0 = &Bb[(8 * ks + t) * BSTR + 16 * g + wn / 8];
            const unsigned* p1 = &Bb[(8 * ks + t + 4) * BSTR + 16 * g + wn / 8];
            *(uint4*)&br0[0] = *(const uint4*)p0;
            *(uint4*)&br0[4] = *(const uint4*)(p0 + 4);
            *(uint4*)&br1[0] = *(const uint4*)p1;
            *(uint4*)&br1[4] = *(const uint4*)(p1 + 4);

            #pragma unroll
            for (int nt = 0; nt < 8; nt++) {
                mma_tf32(acc[0][nt], af[0], br0[nt], br1[nt]);
                mma_tf32(acc[1][nt], af[1], br0[nt], br1[nt]);
            }
        }
        __syncthreads();
    }

    // Epilogue: bias add (+ optional tf32 pre-round), coalesced float2 stores
    #pragma unroll
    for (int mt = 0; mt < 2; mt++) {
        const size_t r0 = (size_t)(brow + wm + mt * 16 + g);
        float* c0 = C + r0 * N;
        float* c1 = c0 + (size_t)8 * N;
        #pragma unroll
        for (int nt = 0; nt < 8; nt++) {
            int nc = bcol + wn + nt * 8 + 2 * t;
            float bx = bias[nc], by = bias[nc + 1];
            float v00 = acc[mt][nt][0] + bx, v01 = acc[mt][nt][1] + by;
            float v10 = acc[mt][nt][2] + bx, v11 = acc[mt][nt][3] + by;
            if (ROUND) {
                v00 = __uint_as_float(f2tf32(v00));
                v01 = __uint_as_float(f2tf32(v01));
                v10 = __uint_as_float(f2tf32(v10));
                v11 = __uint_as_float(f2tf32(v11));
            }
            *(float2*)&c0[nc] = make_float2(v00, v01);
            *(float2*)&c1[nc] = make_float2(v10, v11);
        }
    }
}

// ---------------------------------------------------------------------------
// Tensor-core flash attention (identical to R5 best).
// ---------------------------------------------------------------------------
#define KSTRIDE 68
#define VSTRIDE 72
#define KBUF (64 * KSTRIDE)
#define VBUF (64 * VSTRIDE)
#define ATTN_SMEM ((2 * KBUF + 2 * VBUF) * 4)  // 71680 bytes

__global__ __launch_bounds__(256) void attn_tc_kernel(
    const float* __restrict__ q, const float* __restrict__ kv,
    float* __restrict__ out)
{
    extern __shared__ unsigned sma[];
    unsigned* k_u = sma;              // [2][KBUF]
    unsigned* v_u = sma + 2 * KBUF;   // [2][VBUF]

    const int tid  = threadIdx.x;
    const int w    = tid >> 5;
    const int lane = tid & 31;
    const int g    = lane >> 2;
    const int t    = lane & 3;
    const int bh   = blockIdx.y;
    const int b    = bh / HH;
    const int h    = bh % HH;
    const int q0   = blockIdx.x * 128;

    const float* kvbase = kv + (size_t)b * SS * (2 * DD) + h * (2 * HDD);

    auto load_kv = [&](int kt, int buf) {
        #pragma unroll
        for (int it = 0; it < 4; it++) {
            int idx = it * 256 + tid;
            int row = idx >> 4;
            int c4  = (idx & 15) * 4;
            const float* src = kvbase + (size_t)(kt + row) * (2 * DD) + c4;
            cp16(&k_u[buf * KBUF + row * KSTRIDE + c4], src);
            cp16(&v_u[buf * VBUF + row * VSTRIDE + c4], src + HDD);
        }
        cp_commit();
    };

    load_kv(0, 0);

    // Q fragments (pre-rounded; x0.125 exponent-only => tf32-exact)
    unsigned qa[8][4];
    {
        const float* q0p = q + (size_t)(b * SS + q0 + w * 16 + g) * DD + h * HDD;
        const float* q1p = q0p + (size_t)8 * DD;
        #pragma unroll
        for (int kj = 0; kj < 8; kj++) {
            qa[kj][0] = __float_as_uint(q0p[8 * kj + t]     * 0.125f);
            qa[kj][1] = __float_as_uint(q1p[8 * kj + t]     * 0.125f);
            qa[kj][2] = __float_as_uint(q0p[8 * kj + t + 4] * 0.125f);
            qa[kj][3] = __float_as_uint(q1p[8 * kj + t + 4] * 0.125f);
        }
    }

    float o[8][4];
    #pragma unroll
    for (int i = 0; i < 8; i++)
        #pragma unroll
        for (int j = 0; j < 4; j++) o[i][j] = 0.f;
    float m0 = -INFINITY, m1 = -INFINITY, l0 = 0.f, l1 = 0.f;

    int buf = 0;
    for (int kt = 0; kt < SS; kt += 64, buf ^= 1) {
        if (kt + 64 < SS) { load_kv(kt + 64, buf ^ 1); cp_wait<1>(); }
        else              { cp_wait<0>(); }
        __syncthreads();

        const unsigned* kb = &k_u[buf * KBUF];
        const unsigned* vb = &v_u[buf * VBUF];

        // S = (Q * scale) @ K^T
        float s[8][4];
        #pragma unroll
        for (int nt = 0; nt < 8; nt++) {
            s[nt][0] = s[nt][1] = s[nt][2] = s[nt][3] = 0.f;
            const unsigned* krow = &kb[(8 * nt + g) * KSTRIDE];
            #pragma unroll
            for (int kj = 0; kj < 8; kj++) {
                unsigned b0 = krow[8 * kj + t];
                unsigned b1 = krow[8 * kj + t + 4];
                mma_tf32(s[nt], qa[kj], b0, b1);
            }
        }

        // Online softmax (rows r0 = 16w+g, r1 = r0+8)
        float rmax0 = -INFINITY, rmax1 = -INFINITY;
        #pragma unroll
        for (int nt = 0; nt < 8; nt++) {
            rmax0 = fmaxf(rmax0, fmaxf(s[nt][0], s[nt][1]));
            rmax1 = fmaxf(rmax1, fmaxf(s[nt][2], s[nt][3]));
        }
        rmax0 = fmaxf(rmax0, __shfl_xor_sync(FULLMASK, rmax0, 1));
        rmax0 = fmaxf(rmax0, __shfl_xor_sync(FULLMASK, rmax0, 2));
        rmax1 = fmaxf(rmax1, __shfl_xor_sync(FULLMASK, rmax1, 1));
        rmax1 = fmaxf(rmax1, __shfl_xor_sync(FULLMASK, rmax1, 2));

        const float mn0 = fmaxf(m0, rmax0);
        const float mn1 = fmaxf(m1, rmax1);
        const float cr0 = __expf(m0 - mn0);
        const float cr1 = __expf(m1 - mn1);
        m0 = mn0; m1 = mn1;
        l0 *= cr0; l1 *= cr1;
        #pragma unroll
        for (int nt = 0; nt < 8; nt++) {
            o[nt][0] *= cr0; o[nt][1] *= cr0;
            o[nt][2] *= cr1; o[nt][3] *= cr1;
        }

        // exp, row-sum, P -> A-fragment layout via shuffles
        const int srcA = (lane & 28) | (t >> 1);
        const int srcB = srcA | 2;
        const bool odd = (t & 1);
        unsigned pa[8][4];
        float ls0 = 0.f, ls1 = 0.f;
        #pragma unroll
        for (int nt = 0; nt < 8; nt++) {
            float p0 = __expf(s[nt][0] - mn0);
            float p1 = __expf(s[nt][1] - mn0);
            float p2 = __expf(s[nt][2] - mn1);
            float p3 = __expf(s[nt][3] - mn1);
            ls0 += p0 + p1; ls1 += p2 + p3;
            unsigned e0 = f2tf32(p0), e1 = f2tf32(p1);
            unsigned e2 = f2tf32(p2), e3 = f2tf32(p3);
            unsigned u0 = __shfl_sync(FULLMASK, e0, srcA);
            unsigned u1 = __shfl_sync(FULLMASK, e1, srcA);
            unsigned u2 = __shfl_sync(FULLMASK, e2, srcA);
            unsigned u3 = __shfl_sync(FULLMASK, e3, srcA);
            unsigned w0 = __shfl_sync(FULLMASK, e0, srcB);
            unsigned w1 = __shfl_sync(FULLMASK, e1, srcB);
            unsigned w2 = __shfl_sync(FULLMASK, e2, srcB);
            unsigned w3 = __shfl_sync(FULLMASK, e3, srcB);
            pa[nt][0] = odd ? u1 : u0;
            pa[nt][1] = odd ? u3 : u2;
            pa[nt][2] = odd ? w1 : w0;
            pa[nt][3] = odd ? w3 : w2;
        }
        ls0 += __shfl_xor_sync(FULLMASK, ls0, 1);
        ls0 += __shfl_xor_sync(FULLMASK, ls0, 2);
        ls1 += __shfl_xor_sync(FULLMASK, ls1, 1);
        ls1 += __shfl_xor_sync(FULLMASK, ls1, 2);
        l0 += ls0; l1 += ls1;

        // O += P @ V
        #pragma unroll
        for (int nd = 0; nd < 8; nd++) {
            #pragma unroll
            for (int kj = 0; kj < 8; kj++) {
                unsigned b0 = vb[(8 * kj + t)     * VSTRIDE + 8 * nd + g];
                unsigned b1 = vb[(8 * kj + t + 4) * VSTRIDE + 8 * nd + g];
                mma_tf32(o[nd], pa[kj], b0, b1);
            }
        }
        __syncthreads();
    }

    // normalize + pre-round + store in (B,H,S,HD) layout
    const float inv0 = 1.f / l0;
    const float inv1 = 1.f / l1;
    const size_t r0 = (size_t)(b * HH + h) * SS + q0 + w * 16 + g;
    float* o0 = out + r0 * HDD;
    float* o1 = o0 + (size_t)8 * HDD;
    #pragma unroll
    for (int nt = 0; nt < 8; nt++) {
        int col = 8 * nt + 2 * t;
        float2 t0 = make_float2(__uint_as_float(f2tf32(o[nt][0] * inv0)),
                                __uint_as_float(f2tf32(o[nt][1] * inv0)));
        float2 t1 = make_float2(__uint_as_float(f2tf32(o[nt][2] * inv1)),
                                __uint_as_float(f2tf32(o[nt][3] * inv1)));
        *(float2*)&o0[col] = t0;
        *(float2*)&o1[col] = t1;
    }
}

// ---------------------------------------------------------------------------
extern "C" void kernel_launch(void* const* d_in, const int* in_sizes, int n_in,
                              void* d_out, int out_size)
{
    const float* x    = (const float*)d_in[0];
    const float* y    = (const float*)d_in[1];
    const float* W_kv = (const float*)d_in[2];
    const float* b_kv = (const float*)d_in[3];
    const float* W_q  = (const float*)d_in[4];
    const float* b_q  = (const float*)d_in[5];
    const float* W_o  = (const float*)d_in[6];
    const float* b_o  = (const float*)d_in[7];
    float* out = (float*)d_out;

    float *kvp, *qp, *avp;
    unsigned *xc, *yc, *wkvc, *wqc, *woc;
    cudaGetSymbolAddress((void**)&kvp,  g_kv);
    cudaGetSymbolAddress((void**)&qp,   g_q);
    cudaGetSymbolAddress((void**)&avp,  g_av);
    cudaGetSymbolAddress((void**)&xc,   g_xc);
    cudaGetSymbolAddress((void**)&yc,   g_yc);
    cudaGetSymbolAddress((void**)&wkvc, g_wkvc);
    cudaGetSymbolAddress((void**)&wqc,  g_wqc);
    cudaGetSymbolAddress((void**)&woc,  g_woc);

    cudaFuncSetAttribute(gemm_tc_kernel<1>,
        cudaFuncAttributeMaxDynamicSharedMemorySize, GEMM_SMEM);
    cudaFuncSetAttribute(gemm_tc_kernel<0>,
        cudaFuncAttributeMaxDynamicSharedMemorySize, GEMM_SMEM);
    cudaFuncSetAttribute(attn_tc_kernel,
        cudaFuncAttributeMaxDynamicSharedMemorySize, ATTN_SMEM);

    dim3 blk(256);

    // Pre-round (+ permute for B operands); grid-stride x4 for MLP
    cvtA_kernel<<<256, blk>>>(x, xc, MR * DD / 4);
    cvtA_kernel<<<256, blk>>>(y, yc, MR * DD / 4);
    cvtB_kernel<<<256, blk>>>(W_kv, wkvc, DD * 2 * DD / 4);
    cvtB_kernel<<<256, blk>>>(W_q, wqc, DD * DD / 4);
    cvtB_kernel<<<256, blk>>>(W_o, woc, DD * DD / 4);

    // kv = x @ W_kv + b_kv, output rounded
    gemm_tc_kernel<1><<<dim3((2 * DD) / TBN, MR / TBM), blk, GEMM_SMEM>>>(
        xc, wkvc, b_kv, kvp, MR, 2 * DD, DD);
    // q = y @ W_q + b_q, output rounded
    gemm_tc_kernel<1><<<dim3(DD / TBN, MR / TBM), blk, GEMM_SMEM>>>(
        yc, wqc, b_q, qp, MR, DD, DD);

    // fused attention -> g_av (rounded, (B,H,S,HD) layout)
    attn_tc_kernel<<<dim3(SS / 128, BB * HH), blk, ATTN_SMEM>>>(qp, kvp, avp);

    // out = values @ W_o + b_o (plain output)
    gemm_tc_kernel<0><<<dim3(DD / TBN, MR / TBM), blk, GEMM_SMEM>>>(
        (const unsigned*)avp, woc, b_o, out, MR, DD, DD);
}

// round 8
// speedup vs baseline: 1.1247x; 1.0777x over previous
#include <cuda_runtime.h>
#include <math.h>

#define BB 2
#define SS 2048
#define DD 1024
#define HH 16
#define HDD 64
#define MR (BB*SS)   // 4096 rows

// Scratch (allocation-free rule: __device__ globals)
__device__ __align__(16) float    g_kv[MR * 2 * DD];   // kv proj out (tf32-rounded)
__device__ __align__(16) float    g_q [MR * DD];       // q  proj out (tf32-rounded)
__device__ __align__(16) float    g_av[MR * DD];       // attn out (B,H,S,HD), rounded
__device__ __align__(16) unsigned g_xc  [MR * DD];     // x     tf32 bits
__device__ __align__(16) unsigned g_yc  [MR * DD];     // y     tf32 bits
__device__ __align__(16) unsigned g_wkvc[DD * 2 * DD]; // W_kv  tf32 bits
__device__ __align__(16) unsigned g_wqc [DD * DD];     // W_q   tf32 bits
__device__ __align__(16) unsigned g_woc [DD * DD];     // W_o   tf32 bits

#define FULLMASK 0xffffffffu

__device__ __forceinline__ unsigned f2tf32(float f) {
    unsigned u;
    asm("cvt.rna.tf32.f32 %0, %1;" : "=r"(u) : "f"(f));
    return u;
}

__device__ __forceinline__ void mma_tf32(float* d, const unsigned* a,
                                         unsigned b0, unsigned b1) {
    asm volatile(
        "mma.sync.aligned.m16n8k8.row.col.f32.tf32.tf32.f32 "
        "{%0,%1,%2,%3}, {%4,%5,%6,%7}, {%8,%9}, {%0,%1,%2,%3};\n"
        : "+f"(d[0]), "+f"(d[1]), "+f"(d[2]), "+f"(d[3])
        : "r"(a[0]), "r"(a[1]), "r"(a[2]), "r"(a[3]), "r"(b0), "r"(b1));
}

__device__ __forceinline__ void cp16(void* dst_smem, const void* src) {
    unsigned d = (unsigned)__cvta_generic_to_shared(dst_smem);
    asm volatile("cp.async.cg.shared.global [%0], [%1], 16;\n" :: "r"(d), "l"(src));
}
__device__ __forceinline__ void cp_commit() {
    asm volatile("cp.async.commit_group;\n");
}
template <int N> __device__ __forceinline__ void cp_wait() {
    asm volatile("cp.async.wait_group %0;\n" :: "n"(N));
}

// ---------------------------------------------------------------------------
// Pre-round pass: fp32 -> tf32-rna bit patterns (vectorized)
// ---------------------------------------------------------------------------
__global__ __launch_bounds__(256) void cvt_tf32_kernel(
    const float* __restrict__ src, unsigned* __restrict__ dst, int n4)
{
    int i = blockIdx.x * 256 + threadIdx.x;
    if (i < n4) {
        float4 v = *(const float4*)(src + 4 * (size_t)i);
        uint4 u = make_uint4(f2tf32(v.x), f2tf32(v.y), f2tf32(v.z), f2tf32(v.w));
        *(uint4*)(dst + 4 * (size_t)i) = u;
    }
}

// ---------------------------------------------------------------------------
// Tensor-core tf32 GEMM, 3-stage cp.async pipeline, ONE barrier per K-tile.
// Inputs pre-rounded tf32 bit patterns (no cvt in the loop).
// 128x128 block tile, BK=32, 8 warps (4m x 2n), warp tile 32x64.
// As[m][k] stride 36 (frag bank 4g+t, CF); Bs[k][n] stride 136 (8t+g, CF).
// ROUND: epilogue pre-rounds output to tf32 for the next consumer.
// ---------------------------------------------------------------------------
#define TBM 128
#define TBN 128
#define TBK 32
#define ASTR 36
#define BSTR 136
#define ABUF (TBM * ASTR)   // 4608 words
#define BBUF (TBK * BSTR)   // 4352 words
#define NSTAGE 3
#define GEMM_SMEM (NSTAGE * (ABUF + BBUF) * 4)  // 107520 bytes

template <bool ROUND>
__global__ __launch_bounds__(256) void gemm_tc_kernel(
    const unsigned* __restrict__ A, const unsigned* __restrict__ Bm,
    const float* __restrict__ bias, float* __restrict__ C,
    int M, int N, int K)
{
    extern __shared__ unsigned smg[];
    unsigned* As = smg;                      // [NSTAGE][ABUF]
    unsigned* Bs = smg + NSTAGE * ABUF;      // [NSTAGE][BBUF]

    const int tid  = threadIdx.x;
    const int w    = tid >> 5;
    const int lane = tid & 31;
    const int g    = lane >> 2;
    const int t    = lane & 3;
    const int wm   = (w & 3) * 32;
    const int wn   = (w >> 2) * 64;
    const int brow = blockIdx.y * TBM;
    const int bcol = blockIdx.x * TBN;

    float acc[2][8][4];
    #pragma unroll
    for (int mt = 0; mt < 2; mt++)
        #pragma unroll
        for (int nt = 0; nt < 8; nt++)
            #pragma unroll
            for (int j = 0; j < 4; j++) acc[mt][nt][j] = 0.f;

    auto load_tile = [&](int k0, int buf) {
        #pragma unroll
        for (int it = 0; it < 4; it++) {
            int i  = it * 256 + tid;
            int m  = i >> 3;
            int c4 = (i & 7) * 4;
            cp16(&As[buf * ABUF + m * ASTR + c4],
                 A + (size_t)(brow + m) * K + k0 + c4);
        }
        #pragma unroll
        for (int it = 0; it < 4; it++) {
            int i  = it * 256 + tid;
            int kk = i >> 5;
            int c4 = (i & 31) * 4;
            cp16(&Bs[buf * BBUF + kk * BSTR + c4],
                 Bm + (size_t)(k0 + kk) * N + bcol + c4);
        }
        cp_commit();
    };

    const int ntiles = K / TBK;
    load_tile(0, 0);
    if (ntiles > 1) load_tile(TBK, 1);

    for (int i = 0; i < ntiles; i++) {
        if (i + 1 < ntiles) cp_wait<1>();
        else                cp_wait<0>();
        __syncthreads();   // single barrier: also protects buf (i+2)%3 reuse
        if (i + 2 < ntiles) load_tile((i + 2) * TBK, (i + 2) % NSTAGE);

        const unsigned* Ab = &As[(i % NSTAGE) * ABUF];
        const unsigned* Bb = &Bs[(i % NSTAGE) * BBUF];
        #pragma unroll
        for (int ks = 0; ks < TBK / 8; ks++) {
            unsigned af[2][4];
            #pragma unroll
            for (int mt = 0; mt < 2; mt++) {
                const unsigned* ab = &Ab[(wm + mt * 16) * ASTR + ks * 8];
                af[mt][0] = ab[g * ASTR + t];
                af[mt][1] = ab[(g + 8) * ASTR + t];
                af[mt][2] = ab[g * ASTR + t + 4];
                af[mt][3] = ab[(g + 8) * ASTR + t + 4];
            }
            const unsigned* bb0 = &Bb[(ks * 8 + t) * BSTR + wn + g];
            const unsigned* bb1 = &Bb[(ks * 8 + t + 4) * BSTR + wn + g];
            #pragma unroll
            for (int nt = 0; nt < 8; nt++) {
                unsigned b0 = bb0[nt * 8];
                unsigned b1 = bb1[nt * 8];
                mma_tf32(acc[0][nt], af[0], b0, b1);
                mma_tf32(acc[1][nt], af[1], b0, b1);
            }
        }
    }

    // Epilogue: bias add (+ optional tf32 pre-round), coalesced float2 stores
    #pragma unroll
    for (int mt = 0; mt < 2; mt++) {
        const size_t r0 = (size_t)(brow + wm + mt * 16 + g);
        float* c0 = C + r0 * N;
        float* c1 = c0 + (size_t)8 * N;
        #pragma unroll
        for (int nt = 0; nt < 8; nt++) {
            int nc = bcol + wn + nt * 8 + 2 * t;
            float bx = bias[nc], by = bias[nc + 1];
            float v00 = acc[mt][nt][0] + bx, v01 = acc[mt][nt][1] + by;
            float v10 = acc[mt][nt][2] + bx, v11 = acc[mt][nt][3] + by;
            if (ROUND) {
                v00 = __uint_as_float(f2tf32(v00));
                v01 = __uint_as_float(f2tf32(v01));
                v10 = __uint_as_float(f2tf32(v10));
                v11 = __uint_as_float(f2tf32(v11));
            }
            *(float2*)&c0[nc] = make_float2(v00, v01);
            *(float2*)&c1[nc] = make_float2(v10, v11);
        }
    }
}

// ---------------------------------------------------------------------------
// Tensor-core flash attention, 3-stage cp.async pipeline, one barrier/tile.
// Same math as the R5 kernel (best so far), only the pipeline changed.
// ---------------------------------------------------------------------------
#define KSTRIDE 68
#define VSTRIDE 72
#define KBUF (64 * KSTRIDE)   // 4352 words
#define VBUF (64 * VSTRIDE)   // 4608 words
#define ATTN_SMEM (NSTAGE * (KBUF + VBUF) * 4)  // 107520 bytes

__global__ __launch_bounds__(256) void attn_tc_kernel(
    const float* __restrict__ q, const float* __restrict__ kv,
    float* __restrict__ out)
{
    extern __shared__ unsigned sma[];
    unsigned* k_u = sma;                   // [NSTAGE][KBUF]
    unsigned* v_u = sma + NSTAGE * KBUF;   // [NSTAGE][VBUF]

    const int tid  = threadIdx.x;
    const int w    = tid >> 5;
    const int lane = tid & 31;
    const int g    = lane >> 2;
    const int t    = lane & 3;
    const int bh   = blockIdx.y;
    const int b    = bh / HH;
    const int h    = bh % HH;
    const int q0   = blockIdx.x * 128;

    const float* kvbase = kv + (size_t)b * SS * (2 * DD) + h * (2 * HDD);

    auto load_kv = [&](int kt, int buf) {
        #pragma unroll
        for (int it = 0; it < 4; it++) {
            int idx = it * 256 + tid;
            int row = idx >> 4;
            int c4  = (idx & 15) * 4;
            const float* src = kvbase + (size_t)(kt + row) * (2 * DD) + c4;
            cp16(&k_u[buf * KBUF + row * KSTRIDE + c4], src);
            cp16(&v_u[buf * VBUF + row * VSTRIDE + c4], src + HDD);
        }
        cp_commit();
    };

    load_kv(0, 0);
    load_kv(64, 1);

    // Q fragments (pre-rounded; x0.125 exponent-only => tf32-exact)
    unsigned qa[8][4];
    {
        const float* q0p = q + (size_t)(b * SS + q0 + w * 16 + g) * DD + h * HDD;
        const float* q1p = q0p + (size_t)8 * DD;
        #pragma unroll
        for (int kj = 0; kj < 8; kj++) {
            qa[kj][0] = __float_as_uint(q0p[8 * kj + t]     * 0.125f);
            qa[kj][1] = __float_as_uint(q1p[8 * kj + t]     * 0.125f);
            qa[kj][2] = __float_as_uint(q0p[8 * kj + t + 4] * 0.125f);
            qa[kj][3] = __float_as_uint(q1p[8 * kj + t + 4] * 0.125f);
        }
    }

    float o[8][4];
    #pragma unroll
    for (int i = 0; i < 8; i++)
        #pragma unroll
        for (int j = 0; j < 4; j++) o[i][j] = 0.f;
    float m0 = -INFINITY, m1 = -INFINITY, l0 = 0.f, l1 = 0.f;

    const int ntiles = SS / 64;   // 32
    for (int i = 0; i < ntiles; i++) {
        if (i + 1 < ntiles) cp_wait<1>();
        else                cp_wait<0>();
        __syncthreads();   // single barrier: also protects buf (i+2)%3 reuse
        if (i + 2 < ntiles) load_kv((i + 2) * 64, (i + 2) % NSTAGE);

        const unsigned* kb = &k_u[(i % NSTAGE) * KBUF];
        const unsigned* vb = &v_u[(i % NSTAGE) * VBUF];

        // S = (Q * scale) @ K^T
        float s[8][4];
        #pragma unroll
        for (int nt = 0; nt < 8; nt++) {
            s[nt][0] = s[nt][1] = s[nt][2] = s[nt][3] = 0.f;
            const unsigned* krow = &kb[(8 * nt + g) * KSTRIDE];
            #pragma unroll
            for (int kj = 0; kj < 8; kj++) {
                unsigned b0 = krow[8 * kj + t];
                unsigned b1 = krow[8 * kj + t + 4];
                mma_tf32(s[nt], qa[kj], b0, b1);
            }
        }

        // Online softmax (rows r0 = 16w+g, r1 = r0+8)
        float rmax0 = -INFINITY, rmax1 = -INFINITY;
        #pragma unroll
        for (int nt = 0; nt < 8; nt++) {
            rmax0 = fmaxf(rmax0, fmaxf(s[nt][0], s[nt][1]));
            rmax1 = fmaxf(rmax1, fmaxf(s[nt][2], s[nt][3]));
        }
        rmax0 = fmaxf(rmax0, __shfl_xor_sync(FULLMASK, rmax0, 1));
        rmax0 = fmaxf(rmax0, __shfl_xor_sync(FULLMASK, rmax0, 2));
        rmax1 = fmaxf(rmax1, __shfl_xor_sync(FULLMASK, rmax1, 1));
        rmax1 = fmaxf(rmax1, __shfl_xor_sync(FULLMASK, rmax1, 2));

        const float mn0 = fmaxf(m0, rmax0);
        const float mn1 = fmaxf(m1, rmax1);
        const float cr0 = __expf(m0 - mn0);
        const float cr1 = __expf(m1 - mn1);
        m0 = mn0; m1 = mn1;
        l0 *= cr0; l1 *= cr1;
        #pragma unroll
        for (int nt = 0; nt < 8; nt++) {
            o[nt][0] *= cr0; o[nt][1] *= cr0;
            o[nt][2] *= cr1; o[nt][3] *= cr1;
        }

        // exp, row-sum, P -> A-fragment layout via shuffles
        const int srcA = (lane & 28) | (t >> 1);
        const int srcB = srcA | 2;
        const bool odd = (t & 1);
        unsigned pa[8][4];
        float ls0 = 0.f, ls1 = 0.f;
        #pragma unroll
        for (int nt = 0; nt < 8; nt++) {
            float p0 = __expf(s[nt][0] - mn0);
            float p1 = __expf(s[nt][1] - mn0);
            float p2 = __expf(s[nt][2] - mn1);
            float p3 = __expf(s[nt][3] - mn1);
            ls0 += p0 + p1; ls1 += p2 + p3;
            unsigned e0 = f2tf32(p0), e1 = f2tf32(p1);
            unsigned e2 = f2tf32(p2), e3 = f2tf32(p3);
            unsigned u0 = __shfl_sync(FULLMASK, e0, srcA);
            unsigned u1 = __shfl_sync(FULLMASK, e1, srcA);
            unsigned u2 = __shfl_sync(FULLMASK, e2, srcA);
            unsigned u3 = __shfl_sync(FULLMASK, e3, srcA);
            unsigned w0 = __shfl_sync(FULLMASK, e0, srcB);
            unsigned w1 = __shfl_sync(FULLMASK, e1, srcB);
            unsigned w2 = __shfl_sync(FULLMASK, e2, srcB);
            unsigned w3 = __shfl_sync(FULLMASK, e3, srcB);
            pa[nt][0] = odd ? u1 : u0;
            pa[nt][1] = odd ? u3 : u2;
            pa[nt][2] = odd ? w1 : w0;
            pa[nt][3] = odd ? w3 : w2;
        }
        ls0 += __shfl_xor_sync(FULLMASK, ls0, 1);
        ls0 += __shfl_xor_sync(FULLMASK, ls0, 2);
        ls1 += __shfl_xor_sync(FULLMASK, ls1, 1);
        ls1 += __shfl_xor_sync(FULLMASK, ls1, 2);
        l0 += ls0; l1 += ls1;

        // O += P @ V
        #pragma unroll
        for (int nd = 0; nd < 8; nd++) {
            #pragma unroll
            for (int kj = 0; kj < 8; kj++) {
                unsigned b0 = vb[(8 * kj + t)     * VSTRIDE + 8 * nd + g];
                unsigned b1 = vb[(8 * kj + t + 4) * VSTRIDE + 8 * nd + g];
                mma_tf32(o[nd], pa[kj], b0, b1);
            }
        }
    }

    // normalize + pre-round + store in (B,H,S,HD) layout
    const float inv0 = 1.f / l0;
    const float inv1 = 1.f / l1;
    const size_t r0 = (size_t)(b * HH + h) * SS + q0 + w * 16 + g;
    float* o0 = out + r0 * HDD;
    float* o1 = o0 + (size_t)8 * HDD;
    #pragma unroll
    for (int nt = 0; nt < 8; nt++) {
        int col = 8 * nt + 2 * t;
        float2 t0 = make_float2(__uint_as_float(f2tf32(o[nt][0] * inv0)),
                                __uint_as_float(f2tf32(o[nt][1] * inv0)));
        float2 t1 = make_float2(__uint_as_float(f2tf32(o[nt][2] * inv1)),
                                __uint_as_float(f2tf32(o[nt][3] * inv1)));
        *(float2*)&o0[col] = t0;
        *(float2*)&o1[col] = t1;
    }
}

// ---------------------------------------------------------------------------
extern "C" void kernel_launch(void* const* d_in, const int* in_sizes, int n_in,
                              void* d_out, int out_size)
{
    const float* x    = (const float*)d_in[0];
    const float* y    = (const float*)d_in[1];
    const float* W_kv = (const float*)d_in[2];
    const float* b_kv = (const float*)d_in[3];
    const float* W_q  = (const float*)d_in[4];
    const float* b_q  = (const float*)d_in[5];
    const float* W_o  = (const float*)d_in[6];
    const float* b_o  = (const float*)d_in[7];
    float* out = (float*)d_out;

    float *kvp, *qp, *avp;
    unsigned *xc, *yc, *wkvc, *wqc, *woc;
    cudaGetSymbolAddress((void**)&kvp,  g_kv);
    cudaGetSymbolAddress((void**)&qp,   g_q);
    cudaGetSymbolAddress((void**)&avp,  g_av);
    cudaGetSymbolAddress((void**)&xc,   g_xc);
    cudaGetSymbolAddress((void**)&yc,   g_yc);
    cudaGetSymbolAddress((void**)&wkvc, g_wkvc);
    cudaGetSymbolAddress((void**)&wqc,  g_wqc);
    cudaGetSymbolAddress((void**)&woc,  g_woc);

    cudaFuncSetAttribute(gemm_tc_kernel<true>,
        cudaFuncAttributeMaxDynamicSharedMemorySize, GEMM_SMEM);
    cudaFuncSetAttribute(gemm_tc_kernel<false>,
        cudaFuncAttributeMaxDynamicSharedMemorySize, GEMM_SMEM);
    cudaFuncSetAttribute(attn_tc_kernel,
        cudaFuncAttributeMaxDynamicSharedMemorySize, ATTN_SMEM);

    dim3 blk(256);

    // Pre-round inputs to tf32 bit patterns
    cvt_tf32_kernel<<<(MR * DD / 4 + 255) / 256, blk>>>(x, xc, MR * DD / 4);
    cvt_tf32_kernel<<<(MR * DD / 4 + 255) / 256, blk>>>(y, yc, MR * DD / 4);
    cvt_tf32_kernel<<<(DD * 2 * DD / 4 + 255) / 256, blk>>>(W_kv, wkvc, DD * 2 * DD / 4);
    cvt_tf32_kernel<<<(DD * DD / 4 + 255) / 256, blk>>>(W_q, wqc, DD * DD / 4);
    cvt_tf32_kernel<<<(DD * DD / 4 + 255) / 256, blk>>>(W_o, woc, DD * DD / 4);

    // kv = x @ W_kv + b_kv   [4096 x 2048], output pre-rounded
    gemm_tc_kernel<true><<<dim3((2 * DD) / TBN, MR / TBM), blk, GEMM_SMEM>>>(
        xc, wkvc, b_kv, kvp, MR, 2 * DD, DD);
    // q = y @ W_q + b_q      [4096 x 1024], output pre-rounded
    gemm_tc_kernel<true><<<dim3(DD / TBN, MR / TBM), blk, GEMM_SMEM>>>(
        yc, wqc, b_q, qp, MR, DD, DD);

    // fused tensor-core attention -> values in (B,H,S,HD) layout (pre-rounded)
    attn_tc_kernel<<<dim3(SS / 128, BB * HH), blk, ATTN_SMEM>>>(qp, kvp, avp);

    // out = values @ W_o + b_o [4096 x 1024], final output NOT rounded
    gemm_tc_kernel<false><<<dim3(DD / TBN, MR / TBM), blk, GEMM_SMEM>>>(
        (const unsigned*)avp, woc, b_o, out, MR, DD, DD);
}

// round 10
// speedup vs baseline: 1.1358x; 1.0099x over previous
#include <cuda_runtime.h>
#include <math.h>
#include <stdint.h>

#define BB 2
#define SS 2048
#define DD 1024
#define HH 16
#define HDD 64
#define MR (BB*SS)   // 4096 rows

// Scratch (allocation-free rule: __device__ globals)
__device__ __align__(16) float    g_kv[MR * 2 * DD];   // kv proj out (tf32-rounded)
__device__ __align__(16) float    g_q [MR * DD];       // q  proj out (tf32-rounded)
__device__ __align__(16) float    g_av[MR * DD];       // attn out (B,H,S,HD), rounded
__device__ __align__(16) unsigned g_xc  [MR * DD];     // x     tf32 bits
__device__ __align__(16) unsigned g_yc  [MR * DD];     // y     tf32 bits
__device__ __align__(16) unsigned g_wkvc[DD * 2 * DD]; // W_kv  tf32 bits
__device__ __align__(16) unsigned g_wqc [DD * DD];     // W_q   tf32 bits
__device__ __align__(16) unsigned g_woc [DD * DD];     // W_o   tf32 bits

#define FULLMASK 0xffffffffu

__device__ __forceinline__ unsigned f2tf32(float f) {
    unsigned u;
    asm("cvt.rna.tf32.f32 %0, %1;" : "=r"(u) : "f"(f));
    return u;
}

__device__ __forceinline__ float ex2f(float x) {
    float y;
    asm("ex2.approx.f32 %0, %1;" : "=f"(y) : "f"(x));
    return y;
}

__device__ __forceinline__ void mma_tf32(float* d, const unsigned* a,
                                         unsigned b0, unsigned b1) {
    asm volatile(
        "mma.sync.aligned.m16n8k8.row.col.f32.tf32.tf32.f32 "
        "{%0,%1,%2,%3}, {%4,%5,%6,%7}, {%8,%9}, {%0,%1,%2,%3};\n"
        : "+f"(d[0]), "+f"(d[1]), "+f"(d[2]), "+f"(d[3])
        : "r"(a[0]), "r"(a[1]), "r"(a[2]), "r"(a[3]), "r"(b0), "r"(b1));
}

__device__ __forceinline__ void cp16(void* dst_smem, const void* src) {
    unsigned d = (unsigned)__cvta_generic_to_shared(dst_smem);
    asm volatile("cp.async.cg.shared.global [%0], [%1], 16;\n" :: "r"(d), "l"(src));
}
__device__ __forceinline__ void cp_commit() {
    asm volatile("cp.async.commit_group;\n");
}
template <int N> __device__ __forceinline__ void cp_wait() {
    asm volatile("cp.async.wait_group %0;\n" :: "n"(N));
}

// ---------------------------------------------------------------------------
// Pre-round passes: fp32 -> tf32-rna bit patterns
// ---------------------------------------------------------------------------
__global__ __launch_bounds__(256) void cvt_tf32_kernel(
    const float* __restrict__ src, unsigned* __restrict__ dst, int n4)
{
    int i = blockIdx.x * 256 + threadIdx.x;
    if (i < n4) {
        float4 v = *(const float4*)(src + 4 * (size_t)i);
        uint4 u = make_uint4(f2tf32(v.x), f2tf32(v.y), f2tf32(v.z), f2tf32(v.w));
        *(uint4*)(dst + 4 * (size_t)i) = u;
    }
}

// fused pass for x and y (same size)
__global__ __launch_bounds__(256) void cvt2_tf32_kernel(
    const float* __restrict__ a, unsigned* __restrict__ da,
    const float* __restrict__ b, unsigned* __restrict__ db, int n4each)
{
    int i = blockIdx.x * 256 + threadIdx.x;
    const float* s; unsigned* d;
    if (i < n4each) { s = a; d = da; }
    else            { s = b; d = db; i -= n4each; }
    if (i < n4each) {
        float4 v = *(const float4*)(s + 4 * (size_t)i);
        uint4 u = make_uint4(f2tf32(v.x), f2tf32(v.y), f2tf32(v.z), f2tf32(v.w));
        *(uint4*)(d + 4 * (size_t)i) = u;
    }
}

// ---------------------------------------------------------------------------
// Tensor-core tf32 GEMM body, 3-stage cp.async pipeline, one barrier/K-tile.
// 128x128 block tile, BK=32, 8 warps (4m x 2n), warp tile 32x64.
// As[m][k] stride 36 (frag bank 4g+t, CF); Bs[k][n] stride 136 (8t+g, CF).
// ROUND: epilogue pre-rounds output to tf32 for the next consumer.
// ---------------------------------------------------------------------------
#define TBM 128
#define TBN 128
#define TBK 32
#define ASTR 36
#define BSTR 136
#define ABUF (TBM * ASTR)   // 4608 words
#define BBUF (TBK * BSTR)   // 4352 words
#define NSTAGE 3
#define GEMM_SMEM (NSTAGE * (ABUF + BBUF) * 4)  // 107520 bytes

template <int ROUND>
__device__ __forceinline__ void gemm_body(
    const unsigned* __restrict__ A, const unsigned* __restrict__ Bm,
    const float* __restrict__ bias, float* __restrict__ C,
    int M, int N, int K, int bx, int by, unsigned* smg)
{
    unsigned* As = smg;                      // [NSTAGE][ABUF]
    unsigned* Bs = smg + NSTAGE * ABUF;      // [NSTAGE][BBUF]

    const int tid  = threadIdx.x;
    const int w    = tid >> 5;
    const int lane = tid & 31;
    const int g    = lane >> 2;
    const int t    = lane & 3;
    const int wm   = (w & 3) * 32;
    const int wn   = (w >> 2) * 64;
    const int brow = by * TBM;
    const int bcol = bx * TBN;

    float acc[2][8][4];
    #pragma unroll
    for (int mt = 0; mt < 2; mt++)
        #pragma unroll
        for (int nt = 0; nt < 8; nt++)
            #pragma unroll
            for (int j = 0; j < 4; j++) acc[mt][nt][j] = 0.f;

    auto load_tile = [&](int k0, int buf) {
        #pragma unroll
        for (int it = 0; it < 4; it++) {
            int i  = it * 256 + tid;
            int m  = i >> 3;
            int c4 = (i & 7) * 4;
            cp16(&As[buf * ABUF + m * ASTR + c4],
                 A + (size_t)(brow + m) * K + k0 + c4);
        }
        #pragma unroll
        for (int it = 0; it < 4; it++) {
            int i  = it * 256 + tid;
            int kk = i >> 5;
            int c4 = (i & 31) * 4;
            cp16(&Bs[buf * BBUF + kk * BSTR + c4],
                 Bm + (size_t)(k0 + kk) * N + bcol + c4);
        }
        cp_commit();
    };

    const int ntiles = K / TBK;
    load_tile(0, 0);
    load_tile(TBK, 1);

    for (int i = 0; i < ntiles; i++) {
        if (i + 1 < ntiles) cp_wait<1>();
        else                cp_wait<0>();
        __syncthreads();   // single barrier: also protects buf (i+2)%3 reuse
        if (i + 2 < ntiles) load_tile((i + 2) * TBK, (i + 2) % NSTAGE);

        const unsigned* Ab = &As[(i % NSTAGE) * ABUF];
        const unsigned* Bb = &Bs[(i % NSTAGE) * BBUF];
        #pragma unroll
        for (int ks = 0; ks < TBK / 8; ks++) {
            unsigned af[2][4];
            #pragma unroll
            for (int mt = 0; mt < 2; mt++) {
                const unsigned* ab = &Ab[(wm + mt * 16) * ASTR + ks * 8];
                af[mt][0] = ab[g * ASTR + t];
                af[mt][1] = ab[(g + 8) * ASTR + t];
                af[mt][2] = ab[g * ASTR + t + 4];
                af[mt][3] = ab[(g + 8) * ASTR + t + 4];
            }
            const unsigned* bb0 = &Bb[(ks * 8 + t) * BSTR + wn + g];
            const unsigned* bb1 = &Bb[(ks * 8 + t + 4) * BSTR + wn + g];
            #pragma unroll
            for (int nt = 0; nt < 8; nt++) {
                unsigned b0 = bb0[nt * 8];
                unsigned b1 = bb1[nt * 8];
                mma_tf32(acc[0][nt], af[0], b0, b1);
                mma_tf32(acc[1][nt], af[1], b0, b1);
            }
        }
    }

    // Epilogue: bias add (+ optional tf32 pre-round), coalesced float2 stores
    #pragma unroll
    for (int mt = 0; mt < 2; mt++) {
        const size_t r0 = (size_t)(brow + wm + mt * 16 + g);
        float* c0 = C + r0 * N;
        float* c1 = c0 + (size_t)8 * N;
        #pragma unroll
        for (int nt = 0; nt < 8; nt++) {
            int nc = bcol + wn + nt * 8 + 2 * t;
            float bx2 = bias[nc], by2 = bias[nc + 1];
            float v00 = acc[mt][nt][0] + bx2, v01 = acc[mt][nt][1] + by2;
            float v10 = acc[mt][nt][2] + bx2, v11 = acc[mt][nt][3] + by2;
            if (ROUND) {
                v00 = __uint_as_float(f2tf32(v00));
                v01 = __uint_as_float(f2tf32(v01));
                v10 = __uint_as_float(f2tf32(v10));
                v11 = __uint_as_float(f2tf32(v11));
            }
            *(float2*)&c0[nc] = make_float2(v00, v01);
            *(float2*)&c1[nc] = make_float2(v10, v11);
        }
    }
}

// Fused kv-proj + q-proj: blocks [0,512) do kv (N=2048), [512,768) do q.
__global__ __launch_bounds__(256) void proj_fused_kernel(
    const unsigned* __restrict__ xc, const unsigned* __restrict__ wkv,
    const float* __restrict__ bkv, float* __restrict__ kvp,
    const unsigned* __restrict__ yc, const unsigned* __restrict__ wq,
    const float* __restrict__ bq, float* __restrict__ qp)
{
    extern __shared__ unsigned smg[];
    int bid = blockIdx.x;
    if (bid < 512) {
        gemm_body<1>(xc, wkv, bkv, kvp, MR, 2 * DD, DD, bid & 15, bid >> 4, smg);
    } else {
        int r = bid - 512;
        gemm_body<1>(yc, wq, bq, qp, MR, DD, DD, r & 7, r >> 3, smg);
    }
}

// Plain single GEMM (o-projection, no rounding)
__global__ __launch_bounds__(256) void gemm_single_kernel(
    const unsigned* __restrict__ A, const unsigned* __restrict__ Bm,
    const float* __restrict__ bias, float* __restrict__ C,
    int M, int N, int K)
{
    extern __shared__ unsigned smg[];
    gemm_body<0>(A, Bm, bias, C, M, N, K, blockIdx.x, blockIdx.y, smg);
}

// ---------------------------------------------------------------------------
// Tensor-core flash attention, 3-stage cp.async, log2-domain softmax.
// Q pre-scaled by 0.125*log2e so scores are in log2 domain; all exps are
// single ex2.approx ops. Values of p/l identical to exp domain.
// ---------------------------------------------------------------------------
#define KSTRIDE 68
#define VSTRIDE 72
#define KBUF (64 * KSTRIDE)
#define VBUF (64 * VSTRIDE)
#define ATTN_SMEM (NSTAGE * (KBUF + VBUF) * 4)

__global__ __launch_bounds__(256) void attn_tc_kernel(
    const float* __restrict__ q, const float* __restrict__ kv,
    float* __restrict__ out)
{
    extern __shared__ unsigned sma[];
    unsigned* k_u = sma;
    unsigned* v_u = sma + NSTAGE * KBUF;

    const int tid  = threadIdx.x;
    const int w    = tid >> 5;
    const int lane = tid & 31;
    const int g    = lane >> 2;
    const int t    = lane & 3;
    const int bh   = blockIdx.y;
    const int b    = bh / HH;
    const int h    = bh % HH;
    const int q0   = blockIdx.x * 128;

    const float* kvbase = kv + (size_t)b * SS * (2 * DD) + h * (2 * HDD);

    auto load_kv = [&](int kt, int buf) {
        #pragma unroll
        for (int it = 0; it < 4; it++) {
            int idx = it * 256 + tid;
            int row = idx >> 4;
            int c4  = (idx & 15) * 4;
            const float* src = kvbase + (size_t)(kt + row) * (2 * DD) + c4;
            cp16(&k_u[buf * KBUF + row * KSTRIDE + c4], src);
            cp16(&v_u[buf * VBUF + row * VSTRIDE + c4], src + HDD);
        }
        cp_commit();
    };

    load_kv(0, 0);
    load_kv(64, 1);

    // Q fragments scaled by 0.125*log2e (log2-domain scores)
    const float QSCALE = 0.125f * 1.4426950408889634f;
    unsigned qa[8][4];
    {
        const float* q0p = q + (size_t)(b * SS + q0 + w * 16 + g) * DD + h * HDD;
        const float* q1p = q0p + (size_t)8 * DD;
        #pragma unroll
        for (int kj = 0; kj < 8; kj++) {
            qa[kj][0] = __float_as_uint(q0p[8 * kj + t]     * QSCALE);
            qa[kj][1] = __float_as_uint(q1p[8 * kj + t]     * QSCALE);
            qa[kj][2] = __float_as_uint(q0p[8 * kj + t + 4] * QSCALE);
            qa[kj][3] = __float_as_uint(q1p[8 * kj + t + 4] * QSCALE);
        }
    }

    float o[8][4];
    #pragma unroll
    for (int i = 0; i < 8; i++)
        #pragma unroll
        for (int j = 0; j < 4; j++) o[i][j] = 0.f;
    float m0 = -INFINITY, m1 = -INFINITY, l0 = 0.f, l1 = 0.f;

    const int ntiles = SS / 64;
    for (int i = 0; i < ntiles; i++) {
        if (i + 1 < ntiles) cp_wait<1>();
        else                cp_wait<0>();
        __syncthreads();
        if (i + 2 < ntiles) load_kv((i + 2) * 64, (i + 2) % NSTAGE);

        const unsigned* kb = &k_u[(i % NSTAGE) * KBUF];
        const unsigned* vb = &v_u[(i % NSTAGE) * VBUF];

        // S (log2 domain) = (Q * 0.125 * log2e) @ K^T
        float s[8][4];
        #pragma unroll
        for (int nt = 0; nt < 8; nt++) {
            s[nt][0] = s[nt][1] = s[nt][2] = s[nt][3] = 0.f;
            const unsigned* krow = &kb[(8 * nt + g) * KSTRIDE];
            #pragma unroll
            for (int kj = 0; kj < 8; kj++) {
                unsigned b0 = krow[8 * kj + t];
                unsigned b1 = krow[8 * kj + t + 4];
                mma_tf32(s[nt], qa[kj], b0, b1);
            }
        }

        // Online softmax in log2 domain (rows r0 = 16w+g, r1 = r0+8)
        float rmax0 = -INFINITY, rmax1 = -INFINITY;
        #pragma unroll
        for (int nt = 0; nt < 8; nt++) {
            rmax0 = fmaxf(rmax0, fmaxf(s[nt][0], s[nt][1]));
            rmax1 = fmaxf(rmax1, fmaxf(s[nt][2], s[nt][3]));
        }
        rmax0 = fmaxf(rmax0, __shfl_xor_sync(FULLMASK, rmax0, 1));
        rmax0 = fmaxf(rmax0, __shfl_xor_sync(FULLMASK, rmax0, 2));
        rmax1 = fmaxf(rmax1, __shfl_xor_sync(FULLMASK, rmax1, 1));
        rmax1 = fmaxf(rmax1, __shfl_xor_sync(FULLMASK, rmax1, 2));

        const float mn0 = fmaxf(m0, rmax0);
        const float mn1 = fmaxf(m1, rmax1);
        const float cr0 = ex2f(m0 - mn0);
        const float cr1 = ex2f(m1 - mn1);
        m0 = mn0; m1 = mn1;
        l0 *= cr0; l1 *= cr1;
        #pragma unroll
        for (int nt = 0; nt < 8; nt++) {
            o[nt][0] *= cr0; o[nt][1] *= cr0;
            o[nt][2] *= cr1; o[nt][3] *= cr1;
        }

        // ex2, row-sum, P -> A-fragment layout via shuffles
        const int srcA = (lane & 28) | (t >> 1);
        const int srcB = srcA | 2;
        const bool odd = (t & 1);
        unsigned pa[8][4];
        float ls0 = 0.f, ls1 = 0.f;
        #pragma unroll
        for (int nt = 0; nt < 8; nt++) {
            float p0 = ex2f(s[nt][0] - mn0);
            float p1 = ex2f(s[nt][1] - mn0);
            float p2 = ex2f(s[nt][2] - mn1);
            float p3 = ex2f(s[nt][3] - mn1);
            ls0 += p0 + p1; ls1 += p2 + p3;
            unsigned e0 = f2tf32(p0), e1 = f2tf32(p1);
            unsigned e2 = f2tf32(p2), e3 = f2tf32(p3);
            unsigned u0 = __shfl_sync(FULLMASK, e0, srcA);
            unsigned u1 = __shfl_sync(FULLMASK, e1, srcA);
            unsigned u2 = __shfl_sync(FULLMASK, e2, srcA);
            unsigned u3 = __shfl_sync(FULLMASK, e3, srcA);
            unsigned w0 = __shfl_sync(FULLMASK, e0, srcB);
            unsigned w1 = __shfl_sync(FULLMASK, e1, srcB);
            unsigned w2 = __shfl_sync(FULLMASK, e2, srcB);
            unsigned w3 = __shfl_sync(FULLMASK, e3, srcB);
            pa[nt][0] = odd ? u1 : u0;
            pa[nt][1] = odd ? u3 : u2;
            pa[nt][2] = odd ? w1 : w0;
            pa[nt][3] = odd ? w3 : w2;
        }
        ls0 += __shfl_xor_sync(FULLMASK, ls0, 1);
        ls0 += __shfl_xor_sync(FULLMASK, ls0, 2);
        ls1 += __shfl_xor_sync(FULLMASK, ls1, 1);
        ls1 += __shfl_xor_sync(FULLMASK, ls1, 2);
        l0 += ls0; l1 += ls1;

        // O += P @ V
        #pragma unroll
        for (int nd = 0; nd < 8; nd++) {
            #pragma unroll
            for (int kj = 0; kj < 8; kj++) {
                unsigned b0 = vb[(8 * kj + t)     * VSTRIDE + 8 * nd + g];
                unsigned b1 = vb[(8 * kj + t + 4) * VSTRIDE + 8 * nd + g];
                mma_tf32(o[nd], pa[kj], b0, b1);
            }
        }
    }

    // normalize + pre-round + store in (B,H,S,HD) layout
    const float inv0 = 1.f / l0;
    const float inv1 = 1.f / l1;
    const size_t r0 = (size_t)(b * HH + h) * SS + q0 + w * 16 + g;
    float* o0 = out + r0 * HDD;
    float* o1 = o0 + (size_t)8 * HDD;
    #pragma unroll
    for (int nt = 0; nt < 8; nt++) {
        int col = 8 * nt + 2 * t;
        float2 t0 = make_float2(__uint_as_float(f2tf32(o[nt][0] * inv0)),
                                __uint_as_float(f2tf32(o[nt][1] * inv0)));
        float2 t1 = make_float2(__uint_as_float(f2tf32(o[nt][2] * inv1)),
                                __uint_as_float(f2tf32(o[nt][3] * inv1)));
        *(float2*)&o0[col] = t0;
        *(float2*)&o1[col] = t1;
    }
}

// ---------------------------------------------------------------------------
extern "C" void kernel_launch(void* const* d_in, const int* in_sizes, int n_in,
                              void* d_out, int out_size)
{
    const float* x    = (const float*)d_in[0];
    const float* y    = (const float*)d_in[1];
    const float* W_kv = (const float*)d_in[2];
    const float* b_kv = (const float*)d_in[3];
    const float* W_q  = (const float*)d_in[4];
    const float* b_q  = (const float*)d_in[5];
    const float* W_o  = (const float*)d_in[6];
    const float* b_o  = (const float*)d_in[7];
    float* out = (float*)d_out;

    float *kvp, *qp, *avp;
    unsigned *xc, *yc, *wkvc, *wqc, *woc;
    cudaGetSymbolAddress((void**)&kvp,  g_kv);
    cudaGetSymbolAddress((void**)&qp,   g_q);
    cudaGetSymbolAddress((void**)&avp,  g_av);
    cudaGetSymbolAddress((void**)&xc,   g_xc);
    cudaGetSymbolAddress((void**)&yc,   g_yc);
    cudaGetSymbolAddress((void**)&wkvc, g_wkvc);
    cudaGetSymbolAddress((void**)&wqc,  g_wqc);
    cudaGetSymbolAddress((void**)&woc,  g_woc);

    cudaFuncSetAttribute(proj_fused_kernel,
        cudaFuncAttributeMaxDynamicSharedMemorySize, GEMM_SMEM);
    cudaFuncSetAttribute(gemm_single_kernel,
        cudaFuncAttributeMaxDynamicSharedMemorySize, GEMM_SMEM);
    cudaFuncSetAttribute(attn_tc_kernel,
        cudaFuncAttributeMaxDynamicSharedMemorySize, ATTN_SMEM);

    dim3 blk(256);

    // Pre-round inputs to tf32 bit patterns (x+y fused; weights separate)
    cvt2_tf32_kernel<<<2 * (MR * DD / 4) / 256, blk>>>(
        x, xc, y, yc, MR * DD / 4);
    cvt_tf32_kernel<<<(DD * 2 * DD / 4 + 255) / 256, blk>>>(W_kv, wkvc, DD * 2 * DD / 4);
    cvt_tf32_kernel<<<(DD * DD / 4 + 255) / 256, blk>>>(W_q, wqc, DD * DD / 4);
    cvt_tf32_kernel<<<(DD * DD / 4 + 255) / 256, blk>>>(W_o, woc, DD * DD / 4);

    // Fused kv-proj + q-proj (768 blocks in one launch), outputs pre-rounded
    proj_fused_kernel<<<768, blk, GEMM_SMEM>>>(
        xc, wkvc, b_kv, kvp, yc, wqc, b_q, qp);

    // fused tensor-core attention -> values in (B,H,S,HD) layout (pre-rounded)
    attn_tc_kernel<<<dim3(SS / 128, BB * HH), blk, ATTN_SMEM>>>(qp, kvp, avp);

    // out = values @ W_o + b_o [4096 x 1024], final output NOT rounded
    gemm_single_kernel<<<dim3(DD / TBN, MR / TBM), blk, GEMM_SMEM>>>(
        (const unsigned*)avp, woc, b_o, out, MR, DD, DD);
}